// round 2
// baseline (speedup 1.0000x reference)
#include <cuda_runtime.h>
#include <cstdint>

#define M_DIM 512
#define K_DIM 256
#define O_DIM 256
#define MAGIC 8388608.0f   /* 2^23 */

// ---------------- device scratch (no allocations allowed) ----------------
__device__ unsigned g_amax_bits;           // bits of max |x|
__device__ unsigned g_dmax_bits;           // bits of max(|W|,|b|)
__device__ float g_afT[K_DIM * M_DIM];     // float(aa), transposed [k][m]
__device__ float g_upT[K_DIM * O_DIM];     // |bb|/32,   transposed [k][o]
__device__ int   g_siT[K_DIM * O_DIM];     // sign(bb),  transposed [k][o]
__device__ int   g_cc [O_DIM];             // trunc(b*sn1)

// ---------------- helpers ----------------
__device__ __forceinline__ float san(float v) {
    if (isnan(v)) return 0.0f;
    if (isinf(v)) return 1.0f;
    return v;
}

// sn = 2^floor(log2(floor(32/mx))), replicating JAX fp32 op sequence
__device__ __forceinline__ float calc_sn(unsigned bits) {
    float mx = __uint_as_float(bits);
    if (mx == 0.0f) mx = 1.0f;
    float r = floorf(32.0f / mx);
    return exp2f(floorf(log2f(r)));
}

// ---------------- pass 0: reset maxima (graph replays re-run this) ----------------
__global__ void reset_kernel() {
    g_amax_bits = 0u;
    g_dmax_bits = 0u;
}

// ---------------- pass 1: amax(|x|), dmax(max(|W|,|b|)) ----------------
__global__ void reduce_kernel(const float* __restrict__ x,
                              const float* __restrict__ W,
                              const float* __restrict__ b) {
    float mx = 0.0f, md = 0.0f;
    int t = blockIdx.x * blockDim.x + threadIdx.x;
    int stride = gridDim.x * blockDim.x;
    for (int i = t; i < M_DIM * K_DIM; i += stride) mx = fmaxf(mx, fabsf(san(x[i])));
    for (int i = t; i < O_DIM * K_DIM; i += stride) md = fmaxf(md, fabsf(san(W[i])));
    for (int i = t; i < O_DIM;         i += stride) md = fmaxf(md, fabsf(san(b[i])));
    #pragma unroll
    for (int off = 16; off; off >>= 1) {
        mx = fmaxf(mx, __shfl_xor_sync(0xFFFFFFFFu, mx, off));
        md = fmaxf(md, __shfl_xor_sync(0xFFFFFFFFu, md, off));
    }
    if ((threadIdx.x & 31) == 0) {
        atomicMax(&g_amax_bits, __float_as_uint(mx));
        atomicMax(&g_dmax_bits, __float_as_uint(md));
    }
}

// ---------------- pass 2: quantize into transposed scratch ----------------
__global__ void quant_kernel(const float* __restrict__ x,
                             const float* __restrict__ W,
                             const float* __restrict__ b) {
    float sn1 = calc_sn(g_dmax_bits);
    float sn2 = calc_sn(g_amax_bits);
    int i = blockIdx.x * blockDim.x + threadIdx.x;
    if (i < M_DIM * K_DIM) {
        float v = san(x[i]);
        int m = i / K_DIM, k = i % K_DIM;
        g_afT[k * M_DIM + m] = (float)(int)(v * sn2);
    }
    if (i < O_DIM * K_DIM) {
        float w = san(W[i]);
        int o = i / K_DIM, k = i % K_DIM;
        int bb = (int)(w * sn1);
        int ab = bb < 0 ? -bb : bb;
        g_upT[k * O_DIM + o] = (float)ab * (1.0f / 32.0f);
        g_siT[k * O_DIM + o] = (bb > 0) - (bb < 0);
    }
    if (i < O_DIM) {
        g_cc[i] = (int)(san(b[i]) * sn1);
    }
}

// ---------------- pass 3: LUT-GEMM via FFMA.RM magic floor ----------------
// Block tile 32(m) x 32(o), BK=64, 256 threads (16x16), 2x2 outputs/thread.
#define BM 32
#define BO 32
#define BK 64

__global__ __launch_bounds__(256) void gemm_kernel(float* __restrict__ out) {
    __shared__ float s_a[BK][BM];   // [k][m]
    __shared__ float s_u[BK][BO];   // [k][o]
    __shared__ int   s_s[BK][BO];   // [k][o]

    float sn1 = calc_sn(g_dmax_bits);
    float sn2 = calc_sn(g_amax_bits);

    int tx = threadIdx.x & 15;      // o-dim
    int ty = threadIdx.x >> 4;      // m-dim
    int m0 = blockIdx.y * BM;
    int o0 = blockIdx.x * BO;

    int acc00 = 0, acc01 = 0, acc10 = 0, acc11 = 0;

    for (int kc = 0; kc < K_DIM; kc += BK) {
        // cooperative tile load: each warp covers one 32-float k-row (coalesced)
        #pragma unroll
        for (int i = threadIdx.x; i < BK * BM; i += 256) {
            int kk = i >> 5, mm = i & 31;
            s_a[kk][mm] = g_afT[(kc + kk) * M_DIM + m0 + mm];
            s_u[kk][mm] = g_upT[(kc + kk) * O_DIM + o0 + mm];
            s_s[kk][mm] = g_siT[(kc + kk) * O_DIM + o0 + mm];
        }
        __syncthreads();

        #pragma unroll 16
        for (int k = 0; k < BK; k++) {
            float2 av = *reinterpret_cast<const float2*>(&s_a[k][2 * ty]);
            float2 uv = *reinterpret_cast<const float2*>(&s_u[k][2 * tx]);
            int2   sv = *reinterpret_cast<const int2*>(&s_s[k][2 * tx]);

            int q00 = (int)(__float_as_uint(__fmaf_rd(av.x, uv.x, MAGIC)) & 63u);
            int q01 = (int)(__float_as_uint(__fmaf_rd(av.x, uv.y, MAGIC)) & 63u);
            int q10 = (int)(__float_as_uint(__fmaf_rd(av.y, uv.x, MAGIC)) & 63u);
            int q11 = (int)(__float_as_uint(__fmaf_rd(av.y, uv.y, MAGIC)) & 63u);

            acc00 += sv.x * q00;
            acc01 += sv.y * q01;
            acc10 += sv.x * q10;
            acc11 += sv.y * q11;
        }
        __syncthreads();
    }

    // epilogue: d = trunc(x9/sn2) + cc ; out = d / sn1   (all exact pow2 divides)
    int m = m0 + 2 * ty;
    int o = o0 + 2 * tx;
    int c0 = g_cc[o], c1 = g_cc[o + 1];

    float2 r0, r1;
    r0.x = (float)((int)((float)acc00 / sn2) + c0) / sn1;
    r0.y = (float)((int)((float)acc01 / sn2) + c1) / sn1;
    r1.x = (float)((int)((float)acc10 / sn2) + c0) / sn1;
    r1.y = (float)((int)((float)acc11 / sn2) + c1) / sn1;

    *reinterpret_cast<float2*>(&out[m * O_DIM + o])       = r0;
    *reinterpret_cast<float2*>(&out[(m + 1) * O_DIM + o]) = r1;
}

// ---------------- launch ----------------
extern "C" void kernel_launch(void* const* d_in, const int* in_sizes, int n_in,
                              void* d_out, int out_size) {
    (void)in_sizes; (void)n_in; (void)out_size;
    const float* x = (const float*)d_in[0];
    const float* W = (const float*)d_in[1];
    const float* b = (const float*)d_in[2];
    // d_in[3] (lut) is not needed: lut[i][j] == floor(i*j/32), reproduced exactly
    // by the FFMA.RM magic-floor in the GEMM kernel.

    reset_kernel<<<1, 1>>>();
    reduce_kernel<<<64, 256>>>(x, W, b);
    quant_kernel<<<(M_DIM * K_DIM + 255) / 256, 256>>>(x, W, b);
    dim3 grid(O_DIM / BO, M_DIM / BM);
    gemm_kernel<<<grid, 256>>>((float*)d_out);
}

// round 3
// speedup vs baseline: 1.5000x; 1.5000x over previous
#include <cuda_runtime.h>
#include <cstdint>

#define M_DIM 512
#define K_DIM 256
#define O_DIM 256
#define MAGIC 8388608.0f   /* 2^23 */

#define BM 32
#define BO 32
#define BK 64
#define KSPLIT 4           /* K_DIM / BK */

// ---------------- device scratch (no allocations allowed) ----------------
__device__ unsigned g_amax_bits;                  // bits of max |x|
__device__ unsigned g_dmax_bits;                  // bits of max(|W|,|b|)
__device__ float g_afT[K_DIM * M_DIM];            // float(aa), transposed [k][m]
__device__ float g_upT[K_DIM * O_DIM];            // |bb|/32,   transposed [k][o]
__device__ int   g_siT[K_DIM * O_DIM];            // sign(bb),  transposed [k][o]
__device__ int   g_cc [O_DIM];                    // trunc(b*sn1)
__device__ int   g_part[KSPLIT][M_DIM * O_DIM];   // K-split partial int sums

// ---------------- helpers ----------------
__device__ __forceinline__ float san(float v) {
    if (isnan(v)) return 0.0f;
    if (isinf(v)) return 1.0f;
    return v;
}

// sn = 2^floor(log2(floor(32/mx))); r is a positive integer-valued float,
// so floor(log2(r)) == ilogbf(r) exactly.
__device__ __forceinline__ float calc_sn(unsigned bits) {
    float mx = __uint_as_float(bits);
    if (mx == 0.0f) mx = 1.0f;
    float r = floorf(32.0f / mx);
    return ldexpf(1.0f, ilogbf(r));
}

// ---------------- pass 0: reset maxima (graph replays re-run this) ----------------
__global__ void reset_kernel() {
    g_amax_bits = 0u;
    g_dmax_bits = 0u;
}

// ---------------- pass 1: amax(|x|), dmax(max(|W|,|b|)) ----------------
__global__ void reduce_kernel(const float* __restrict__ x,
                              const float* __restrict__ W,
                              const float* __restrict__ b) {
    float mx = 0.0f, md = 0.0f;
    int t = blockIdx.x * blockDim.x + threadIdx.x;
    int stride = gridDim.x * blockDim.x;
    for (int i = t; i < M_DIM * K_DIM; i += stride) mx = fmaxf(mx, fabsf(san(x[i])));
    for (int i = t; i < O_DIM * K_DIM; i += stride) md = fmaxf(md, fabsf(san(W[i])));
    for (int i = t; i < O_DIM;         i += stride) md = fmaxf(md, fabsf(san(b[i])));
    #pragma unroll
    for (int off = 16; off; off >>= 1) {
        mx = fmaxf(mx, __shfl_xor_sync(0xFFFFFFFFu, mx, off));
        md = fmaxf(md, __shfl_xor_sync(0xFFFFFFFFu, md, off));
    }
    if ((threadIdx.x & 31) == 0) {
        atomicMax(&g_amax_bits, __float_as_uint(mx));
        atomicMax(&g_dmax_bits, __float_as_uint(md));
    }
}

// ---------------- pass 2: quantize into transposed scratch ----------------
__global__ void quant_kernel(const float* __restrict__ x,
                             const float* __restrict__ W,
                             const float* __restrict__ b) {
    float sn1 = calc_sn(g_dmax_bits);
    float sn2 = calc_sn(g_amax_bits);
    int i = blockIdx.x * blockDim.x + threadIdx.x;
    if (i < M_DIM * K_DIM) {
        float v = san(x[i]);
        int m = i / K_DIM, k = i % K_DIM;
        g_afT[k * M_DIM + m] = (float)(int)(v * sn2);
    }
    if (i < O_DIM * K_DIM) {
        float w = san(W[i]);
        int o = i / K_DIM, k = i % K_DIM;
        int bb = (int)(w * sn1);
        int ab = bb < 0 ? -bb : bb;
        g_upT[k * O_DIM + o] = (float)ab * (1.0f / 32.0f);
        g_siT[k * O_DIM + o] = (bb > 0) - (bb < 0);
    }
    if (i < O_DIM) {
        g_cc[i] = (int)(san(b[i]) * sn1);
    }
}

// ---------------- pass 3: K-split LUT-GEMM via FFMA.RM magic floor ----------------
// grid (O/BO=8, M/BM=16, KSPLIT=4) = 512 blocks; one BK=64 smem stage per block.
__global__ __launch_bounds__(256) void gemm_kernel() {
    __shared__ float s_a[BK][BM];   // [k][m]
    __shared__ float s_u[BK][BO];   // [k][o]
    __shared__ int   s_s[BK][BO];   // [k][o]

    int m0 = blockIdx.y * BM;
    int o0 = blockIdx.x * BO;
    int kc = blockIdx.z * BK;

    // cooperative tile load: consecutive threads -> consecutive m/o (coalesced)
    #pragma unroll
    for (int i = threadIdx.x; i < BK * BM; i += 256) {
        int kk = i >> 5, mm = i & 31;
        s_a[kk][mm] = g_afT[(kc + kk) * M_DIM + m0 + mm];
        s_u[kk][mm] = g_upT[(kc + kk) * O_DIM + o0 + mm];
        s_s[kk][mm] = g_siT[(kc + kk) * O_DIM + o0 + mm];
    }
    __syncthreads();

    int tx = threadIdx.x & 15;      // o-dim
    int ty = threadIdx.x >> 4;      // m-dim

    int acc00 = 0, acc01 = 0, acc10 = 0, acc11 = 0;

    #pragma unroll 16
    for (int k = 0; k < BK; k++) {
        float2 av = *reinterpret_cast<const float2*>(&s_a[k][2 * ty]);
        float2 uv = *reinterpret_cast<const float2*>(&s_u[k][2 * tx]);
        int2   sv = *reinterpret_cast<const int2*>(&s_s[k][2 * tx]);

        int q00 = (int)(__float_as_uint(__fmaf_rd(av.x, uv.x, MAGIC)) & 63u);
        int q01 = (int)(__float_as_uint(__fmaf_rd(av.x, uv.y, MAGIC)) & 63u);
        int q10 = (int)(__float_as_uint(__fmaf_rd(av.y, uv.x, MAGIC)) & 63u);
        int q11 = (int)(__float_as_uint(__fmaf_rd(av.y, uv.y, MAGIC)) & 63u);

        acc00 += sv.x * q00;
        acc01 += sv.y * q01;
        acc10 += sv.x * q10;
        acc11 += sv.y * q11;
    }

    // deterministic partial store (no atomics; slot fully overwritten each replay)
    int m = m0 + 2 * ty;
    int o = o0 + 2 * tx;
    int* __restrict__ p = g_part[blockIdx.z];
    *reinterpret_cast<int2*>(&p[m * O_DIM + o])       = make_int2(acc00, acc01);
    *reinterpret_cast<int2*>(&p[(m + 1) * O_DIM + o]) = make_int2(acc10, acc11);
}

// ---------------- pass 4: sum partials + exact pow-2 epilogue ----------------
__global__ __launch_bounds__(256) void epilogue_kernel(float* __restrict__ out) {
    int idx = blockIdx.x * 256 + threadIdx.x;   // grid covers M*O exactly
    float sn1 = calc_sn(g_dmax_bits);
    float sn2 = calc_sn(g_amax_bits);
    int acc = g_part[0][idx] + g_part[1][idx] + g_part[2][idx] + g_part[3][idx];
    int o = idx & (O_DIM - 1);
    // d = trunc(x9/sn2) + cc ; out = d / sn1  (exact pow-2 divides, trunc = C cast)
    out[idx] = (float)((int)((float)acc / sn2) + g_cc[o]) / sn1;
}

// ---------------- launch ----------------
extern "C" void kernel_launch(void* const* d_in, const int* in_sizes, int n_in,
                              void* d_out, int out_size) {
    (void)in_sizes; (void)n_in; (void)out_size;
    const float* x = (const float*)d_in[0];
    const float* W = (const float*)d_in[1];
    const float* b = (const float*)d_in[2];
    // d_in[3] (lut) unused: lut[i][j] == floor(i*j/32), reproduced exactly by
    // the FFMA.RM magic-floor in the GEMM kernel.

    reset_kernel<<<1, 32>>>();
    reduce_kernel<<<64, 256>>>(x, W, b);
    quant_kernel<<<(M_DIM * K_DIM + 255) / 256, 256>>>(x, W, b);
    dim3 grid(O_DIM / BO, M_DIM / BM, KSPLIT);
    gemm_kernel<<<grid, 256>>>();
    epilogue_kernel<<<(M_DIM * O_DIM) / 256, 256>>>((float*)d_out);
}

// round 5
// speedup vs baseline: 1.7054x; 1.1369x over previous
#include <cuda_runtime.h>
#include <cstdint>

#define M_DIM 512
#define K_DIM 256
#define O_DIM 256
#define KSPLIT 4
#define BK 64
#define RBLK 128          /* reduce blocks */

#define BIGF  12582912.0f          /* 1.5 * 2^23 */
#define BIGU  0x4B400000u
#define THETA 0.0009765625f        /* 2^-10 */
#define EPSB  0.000244140625f      /* 2^-12 */

// ---------------- device scratch (no allocations allowed) ----------------
__device__ float2 g_bmax2[RBLK];               // per-block (max|x|, max(|W|,|b|))
__device__ float g_af[M_DIM * K_DIM];          // float(aa) + 2^-10, row-major [m][k]
__device__ float g_us[O_DIM * K_DIM];          // bb/32 (- 2^-12 if bb<0), row-major [o][k]
__device__ int   g_cc[O_DIM];                  // trunc(b*sn1)
__device__ int   g_npart[O_DIM * 8];           // per-o per-32k-chunk count of bb<0
__device__ float g_sn[2];                      // {sn1, sn2}
__device__ int   g_part[KSPLIT][M_DIM * O_DIM];

// ---------------- helpers ----------------
__device__ __forceinline__ float san(float v) {
    if (isnan(v)) return 0.0f;
    if (isinf(v)) return 1.0f;
    return v;
}

// sn = 2^floor(log2(floor(32/mx))); argument of log2 is a positive integer.
__device__ __forceinline__ float calc_sn(float mx) {
    if (mx == 0.0f) mx = 1.0f;
    float r = floorf(32.0f / mx);
    return ldexpf(1.0f, ilogbf(r));
}

// block-level max reduce of (mx, md) over 256 threads; result valid in ALL threads
__device__ __forceinline__ float2 block_max2(float mx, float md) {
    __shared__ float2 s_red[8];
    __shared__ float2 s_out;
    #pragma unroll
    for (int off = 16; off; off >>= 1) {
        mx = fmaxf(mx, __shfl_xor_sync(0xFFFFFFFFu, mx, off));
        md = fmaxf(md, __shfl_xor_sync(0xFFFFFFFFu, md, off));
    }
    if ((threadIdx.x & 31) == 0) s_red[threadIdx.x >> 5] = make_float2(mx, md);
    __syncthreads();
    if (threadIdx.x == 0) {
        float2 r = s_red[0];
        #pragma unroll
        for (int w = 1; w < 8; w++) {
            r.x = fmaxf(r.x, s_red[w].x);
            r.y = fmaxf(r.y, s_red[w].y);
        }
        s_out = r;
    }
    __syncthreads();
    return s_out;
}

// ---------------- pass 1: per-block maxima (no atomics, no reset) ----------------
__global__ __launch_bounds__(256) void reduce_kernel(const float* __restrict__ x,
                                                     const float* __restrict__ W,
                                                     const float* __restrict__ b) {
    float mx = 0.0f, md = 0.0f;
    int t = blockIdx.x * 256 + threadIdx.x;
    const int stride = RBLK * 256;
    for (int i = t; i < M_DIM * K_DIM; i += stride) mx = fmaxf(mx, fabsf(san(x[i])));
    for (int i = t; i < O_DIM * K_DIM; i += stride) md = fmaxf(md, fabsf(san(W[i])));
    md = fmaxf(md, fabsf(san(b[threadIdx.x])));   // 256 threads cover b exactly
    float2 r = block_max2(mx, md);
    if (threadIdx.x == 0) g_bmax2[blockIdx.x] = r;
}

// ---------------- pass 2: quantize (row-major, coalesced) ----------------
__global__ __launch_bounds__(256) void quant_kernel(const float* __restrict__ x,
                                                    const float* __restrict__ W,
                                                    const float* __restrict__ b) {
    // prologue: final max over 128 block results
    float mx = 0.0f, md = 0.0f;
    if (threadIdx.x < RBLK) {
        float2 v = g_bmax2[threadIdx.x];
        mx = v.x; md = v.y;
    }
    float2 r = block_max2(mx, md);
    float sn2 = calc_sn(r.x);
    float sn1 = calc_sn(r.y);

    int i = blockIdx.x * 256 + threadIdx.x;   // grid covers M*K
    // x -> af' = float(trunc(x*sn2)) + 2^-10
    g_af[i] = (float)(int)(san(x[i]) * sn2) + THETA;

    if (i < O_DIM * K_DIM) {
        int bb = (int)(san(W[i]) * sn1);
        float us = (float)bb * (1.0f / 32.0f);
        if (bb < 0) us -= EPSB;
        g_us[i] = us;
        // warp covers 32 consecutive k of one o-row: ballot-count negatives
        unsigned ball = __ballot_sync(0xFFFFFFFFu, bb < 0);
        if ((threadIdx.x & 31) == 0) g_npart[i >> 5] = __popc(ball);
    }
    if (i < O_DIM) g_cc[i] = (int)(san(b[i]) * sn1);
    if (i == 0) { g_sn[0] = sn1; g_sn[1] = sn2; }
}

// ---------------- pass 3: LUT-GEMM, 2 instr/MAC (FFMA.RD + IADD3) ----------------
// grid (8 o-blk, 16 m-blk, KSPLIT); tile 32m x 32o x 64k; 256 threads, 2x2/thread.
__global__ __launch_bounds__(256) void gemm_kernel() {
    __shared__ float s_a[BK][34];   // [k][m], pad 34 keeps float2 aligned, <=4-way STS
    __shared__ float s_u[BK][34];   // [k][o]

    int m0 = blockIdx.y * 32;
    int o0 = blockIdx.x * 32;
    int kc = blockIdx.z * BK;

    // stage: coalesced LDG.128 row-major, transposed STS into smem
    int mm = threadIdx.x >> 3;
    int kg = (threadIdx.x & 7) << 3;
    {
        const float4* pa = (const float4*)&g_af[(m0 + mm) * K_DIM + kc + kg];
        const float4* pu = (const float4*)&g_us[(o0 + mm) * K_DIM + kc + kg];
        float4 a0 = pa[0], a1 = pa[1];
        float4 u0 = pu[0], u1 = pu[1];
        s_a[kg + 0][mm] = a0.x; s_a[kg + 1][mm] = a0.y;
        s_a[kg + 2][mm] = a0.z; s_a[kg + 3][mm] = a0.w;
        s_a[kg + 4][mm] = a1.x; s_a[kg + 5][mm] = a1.y;
        s_a[kg + 6][mm] = a1.z; s_a[kg + 7][mm] = a1.w;
        s_u[kg + 0][mm] = u0.x; s_u[kg + 1][mm] = u0.y;
        s_u[kg + 2][mm] = u0.z; s_u[kg + 3][mm] = u0.w;
        s_u[kg + 4][mm] = u1.x; s_u[kg + 5][mm] = u1.y;
        s_u[kg + 6][mm] = u1.z; s_u[kg + 7][mm] = u1.w;
    }
    __syncthreads();

    int tx = threadIdx.x & 15;      // o
    int ty = threadIdx.x >> 4;      // m

    unsigned acc00 = 0, acc01 = 0, acc10 = 0, acc11 = 0;

    #pragma unroll 16
    for (int k = 0; k < BK; k++) {
        float2 av = *reinterpret_cast<const float2*>(&s_a[k][2 * ty]);
        float2 uv = *reinterpret_cast<const float2*>(&s_u[k][2 * tx]);
        acc00 += __float_as_uint(__fmaf_rd(av.x, uv.x, BIGF));
        acc01 += __float_as_uint(__fmaf_rd(av.x, uv.y, BIGF));
        acc10 += __float_as_uint(__fmaf_rd(av.y, uv.x, BIGF));
        acc11 += __float_as_uint(__fmaf_rd(av.y, uv.y, BIGF));
    }

    const unsigned C = (unsigned)(64u * BIGU);   // mod 2^32 wraparound
    int m = m0 + 2 * ty;
    int o = o0 + 2 * tx;
    int* __restrict__ p = g_part[blockIdx.z];
    *reinterpret_cast<int2*>(&p[m * O_DIM + o]) =
        make_int2((int)(acc00 - C), (int)(acc01 - C));
    *reinterpret_cast<int2*>(&p[(m + 1) * O_DIM + o]) =
        make_int2((int)(acc10 - C), (int)(acc11 - C));
}

// ---------------- pass 4: sum partials + negative-count fix + exact epilogue ----
// 128 blocks; thread t owns column o=t for 4 m-rows (shares N_o, cc).
__global__ __launch_bounds__(256) void epilogue_kernel(float* __restrict__ out) {
    int o = threadIdx.x;
    int mb = blockIdx.x * 4;
    float sn1 = g_sn[0], sn2 = g_sn[1];
    int4 n0 = *reinterpret_cast<const int4*>(&g_npart[o * 8]);
    int4 n1 = *reinterpret_cast<const int4*>(&g_npart[o * 8 + 4]);
    int N = n0.x + n0.y + n0.z + n0.w + n1.x + n1.y + n1.z + n1.w;
    int cc = g_cc[o];
    #pragma unroll
    for (int r = 0; r < 4; r++) {
        int idx = (mb + r) * O_DIM + o;
        int x9 = g_part[0][idx] + g_part[1][idx] + g_part[2][idx] + g_part[3][idx] + N;
        // d = trunc(x9/sn2) + cc ; out = d/sn1 (exact pow-2 ops)
        out[idx] = (float)((int)((float)x9 / sn2) + cc) / sn1;
    }
}

// ---------------- launch ----------------
extern "C" void kernel_launch(void* const* d_in, const int* in_sizes, int n_in,
                              void* d_out, int out_size) {
    (void)in_sizes; (void)n_in; (void)out_size;
    const float* x = (const float*)d_in[0];
    const float* W = (const float*)d_in[1];
    const float* b = (const float*)d_in[2];
    // d_in[3] (lut) unused: lut[i][j] == floor(i*j/32), reproduced exactly by
    // the FFMA.RD magic-floor + raw-bits accumulation.

    reduce_kernel<<<RBLK, 256>>>(x, W, b);
    quant_kernel<<<(M_DIM * K_DIM) / 256, 256>>>(x, W, b);
    dim3 grid(O_DIM / 32, M_DIM / 32, KSPLIT);
    gemm_kernel<<<grid, 256>>>();
    epilogue_kernel<<<M_DIM / 4, 256>>>((float*)d_out);
}